// round 13
// baseline (speedup 1.0000x reference)
#include <cuda_runtime.h>
#include <math.h>

// Problem constants
#define D     1024
#define S     16
#define B     512
#define T     256
#define SCALE 0.03125f   // 1/sqrt(1024)

// ---------------------------------------------------------------------------
// Scratch (device globals — no allocations allowed)
// ---------------------------------------------------------------------------
__device__ float g_q[S * D];          // q = latent @ Wq^T + bq            [16,1024]
__device__ float g_qk[S * D];         // scale * (q @ Wk)                  [16,1024]
__device__ float g_qb[S];             // scale * (q . bk)                  [16]
__device__ float g_Ct[D * D];         // Ct[d][e'] = sum_e Wo[e',e]Wv[e,d] [1024,1024]
__device__ float g_cb[D];             // Wo @ bv + bo                      [1024]
__device__ float g_scores[B * S * T]; // scores -> attn (in place)         [512,16,256]
__device__ float g_Y[B * S * D];      // Y = attn @ X                      [512,16,1024]

// ---------------------------------------------------------------------------
// packed f32x2 FMA (sm_103a): d = a*b + c on two fp32 lanes
// ---------------------------------------------------------------------------
__device__ __forceinline__ float2 ffma2(float2 a, float2 b, float2 c) {
    unsigned long long ra = *reinterpret_cast<unsigned long long*>(&a);
    unsigned long long rb = *reinterpret_cast<unsigned long long*>(&b);
    unsigned long long rc = *reinterpret_cast<unsigned long long*>(&c);
    unsigned long long rd;
    asm("fma.rn.f32x2 %0, %1, %2, %3;" : "=l"(rd) : "l"(ra), "l"(rb), "l"(rc));
    float2 d;
    *reinterpret_cast<unsigned long long*>(&d) = rd;
    return d;
}

// ---------------------------------------------------------------------------
// zero g_qk (needed before the atomic split-K accumulation)
// ---------------------------------------------------------------------------
__global__ void k_zeroqk() {
    g_qk[blockIdx.x * 256 + threadIdx.x] = 0.0f;
}

// ---------------------------------------------------------------------------
// q[s,e] = sum_d latent[s,d] * Wq[e,d] + bq[e]   (warp per e, all 16 s)
// ---------------------------------------------------------------------------
__global__ __launch_bounds__(256) void k_q(const float* __restrict__ latent,
                                           const float* __restrict__ Wq,
                                           const float* __restrict__ bq) {
    int warp = (blockIdx.x * blockDim.x + threadIdx.x) >> 5;  // 0..1023 == e
    int lane = threadIdx.x & 31;
    const float* wrow = Wq + warp * D;
    float acc[S];
#pragma unroll
    for (int s = 0; s < S; s++) acc[s] = 0.0f;
    for (int i = 0; i < D / 32; i++) {
        int d = (i << 5) + lane;
        float w = wrow[d];
#pragma unroll
        for (int s = 0; s < S; s++) acc[s] += w * latent[s * D + d];
    }
#pragma unroll
    for (int s = 0; s < S; s++) {
        float v = acc[s];
#pragma unroll
        for (int off = 16; off; off >>= 1) v += __shfl_xor_sync(0xffffffffu, v, off);
        if (lane == 0) g_q[s * D + warp] = v + bq[warp];
    }
}

// qb[s] = scale * (q[s,:] . bk)
__global__ void k_qb(const float* __restrict__ bk) {
    int warp = threadIdx.x >> 5, lane = threadIdx.x & 31;
    if (warp >= S) return;
    float acc = 0.0f;
    for (int i = lane; i < D; i += 32) acc += g_q[warp * D + i] * bk[i];
#pragma unroll
    for (int off = 16; off; off >>= 1) acc += __shfl_xor_sync(0xffffffffu, acc, off);
    if (lane == 0) g_qb[warp] = acc * SCALE;
}

// qk[s,d] = scale * sum_e q[s,e] * Wk[e,d]   (split over e blocks, atomic add)
__global__ __launch_bounds__(256) void k_qk(const float* __restrict__ Wk) {
    __shared__ float qs[S][64];
    int d  = blockIdx.x * 256 + threadIdx.x;  // 0..1023
    int e0 = blockIdx.y * 64;
    {   // stage q tile [16][64]
        int idx = threadIdx.x;
#pragma unroll
        for (int j = 0; j < 4; j++) {
            int ii = idx + j * 256;
            qs[ii >> 6][ii & 63] = g_q[(ii >> 6) * D + e0 + (ii & 63)];
        }
    }
    __syncthreads();
    float acc[S];
#pragma unroll
    for (int s = 0; s < S; s++) acc[s] = 0.0f;
    for (int e = 0; e < 64; e++) {
        float w = Wk[(e0 + e) * D + d];
#pragma unroll
        for (int s = 0; s < S; s++) acc[s] += w * qs[s][e];
    }
#pragma unroll
    for (int s = 0; s < S; s++) atomicAdd(&g_qk[s * D + d], acc[s] * SCALE);
}

// ---------------------------------------------------------------------------
// Ct[d][e'] = sum_e Wo[e',e] * Wv[e,d]   (64x64x16 tile, 4x4/thread, f32x2)
// ---------------------------------------------------------------------------
__global__ __launch_bounds__(256) void k_C(const float* __restrict__ Wo,
                                           const float* __restrict__ Wv) {
    __shared__ float As[16][64];  // [k][m]  m = e'
    __shared__ float Bs[16][64];  // [k][n]  n = d
    int tid = threadIdx.x;
    int m0b = blockIdx.y * 64, n0b = blockIdx.x * 64;
    int tm = tid & 15, tn = tid >> 4;
    int m0 = tm * 4, n0 = tn * 4;
    int ar = tid >> 2, ac = (tid & 3) * 4;
    int br = tid >> 4, bn = (tid & 15) * 4;
    float2 acc[4][2] = {};
    for (int k0 = 0; k0 < D; k0 += 16) {
        float4 av = *(const float4*)(Wo + (m0b + ar) * D + k0 + ac);
        As[ac + 0][ar] = av.x; As[ac + 1][ar] = av.y;
        As[ac + 2][ar] = av.z; As[ac + 3][ar] = av.w;
        *(float4*)&Bs[br][bn] = *(const float4*)(Wv + (k0 + br) * D + n0b + bn);
        __syncthreads();
#pragma unroll
        for (int k = 0; k < 16; k++) {
            float4 a  = *(const float4*)&As[k][m0];
            float4 bb = *(const float4*)&Bs[k][n0];
            float2 b01 = make_float2(bb.x, bb.y), b23 = make_float2(bb.z, bb.w);
            float am[4] = {a.x, a.y, a.z, a.w};
#pragma unroll
            for (int i = 0; i < 4; i++) {
                float2 aa = make_float2(am[i], am[i]);
                acc[i][0] = ffma2(aa, b01, acc[i][0]);
                acc[i][1] = ffma2(aa, b23, acc[i][1]);
            }
        }
        __syncthreads();
    }
    float(*af)[4] = reinterpret_cast<float(*)[4]>(acc);
#pragma unroll
    for (int j = 0; j < 4; j++) {
        float4 v = make_float4(af[0][j], af[1][j], af[2][j], af[3][j]);
        *(float4*)(g_Ct + (n0b + n0 + j) * D + m0b + m0) = v;
    }
}

// cb[e'] = sum_e Wo[e',e]*bv[e] + bo[e']   (warp per e')
__global__ __launch_bounds__(256) void k_cb(const float* __restrict__ Wo,
                                            const float* __restrict__ bv,
                                            const float* __restrict__ bo) {
    int warp = (blockIdx.x * blockDim.x + threadIdx.x) >> 5;  // 0..1023
    int lane = threadIdx.x & 31;
    float acc = 0.0f;
    for (int i = lane; i < D; i += 32) acc += Wo[warp * D + i] * bv[i];
#pragma unroll
    for (int off = 16; off; off >>= 1) acc += __shfl_xor_sync(0xffffffffu, acc, off);
    if (lane == 0) g_cb[warp] = acc + bo[warp];
}

// ---------------------------------------------------------------------------
// scores[b,s,t] = qk[s,:].X[b,t,:] + qb[s] + imp[b,t]   (per-batch GEMM, N=16)
// ---------------------------------------------------------------------------
__global__ __launch_bounds__(256) void k_scores(const float* __restrict__ X,
                                                const float* __restrict__ imp) {
    __shared__ float Xs[16][256];   // [k (d-sub)][t]
    __shared__ float qks[16][16];   // [k][s]
    int b   = blockIdx.x;
    int tid = threadIdx.x;
    const float* Xb = X + b * (T * D);
    int tm = tid & 63, tn = tid >> 6;
    int m0 = tm * 4, n0 = tn * 4;     // m over t, n over s
    float2 acc[4][2] = {};
    for (int k0 = 0; k0 < D; k0 += 16) {
#pragma unroll
        for (int j = 0; j < 4; j++) {
            float4 v = *(const float4*)(Xb + tid * D + k0 + j * 4);
            Xs[j * 4 + 0][tid] = v.x; Xs[j * 4 + 1][tid] = v.y;
            Xs[j * 4 + 2][tid] = v.z; Xs[j * 4 + 3][tid] = v.w;
        }
        qks[tid & 15][tid >> 4] = g_qk[(tid >> 4) * D + k0 + (tid & 15)];
        __syncthreads();
#pragma unroll
        for (int k = 0; k < 16; k++) {
            float4 a  = *(const float4*)&Xs[k][m0];
            float4 bq = *(const float4*)&qks[k][n0];
            float2 b01 = make_float2(bq.x, bq.y), b23 = make_float2(bq.z, bq.w);
            float am[4] = {a.x, a.y, a.z, a.w};
#pragma unroll
            for (int i = 0; i < 4; i++) {
                float2 aa = make_float2(am[i], am[i]);
                acc[i][0] = ffma2(aa, b01, acc[i][0]);
                acc[i][1] = ffma2(aa, b23, acc[i][1]);
            }
        }
        __syncthreads();
    }
    float4 iv = *(const float4*)(imp + b * T + m0);
    float(*af)[4] = reinterpret_cast<float(*)[4]>(acc);
#pragma unroll
    for (int j = 0; j < 4; j++) {
        int s = n0 + j;
        float qb = g_qb[s];
        float4 v = make_float4(af[0][j] + qb + iv.x, af[1][j] + qb + iv.y,
                               af[2][j] + qb + iv.z, af[3][j] + qb + iv.w);
        *(float4*)(g_scores + (b * S + s) * T + m0) = v;
    }
}

// ---------------------------------------------------------------------------
// softmax over t (row = b*16+s, 256 threads = 256 t)
// ---------------------------------------------------------------------------
__global__ __launch_bounds__(256) void k_softmax() {
    int row = blockIdx.x;
    int tid = threadIdx.x;
    int warp = tid >> 5, lane = tid & 31;
    __shared__ float red[8];
    float v = g_scores[row * T + tid];
    float m = v;
#pragma unroll
    for (int off = 16; off; off >>= 1) m = fmaxf(m, __shfl_xor_sync(0xffffffffu, m, off));
    if (lane == 0) red[warp] = m;
    __syncthreads();
    float mx = red[0];
#pragma unroll
    for (int i = 1; i < 8; i++) mx = fmaxf(mx, red[i]);
    __syncthreads();
    float e = expf(v - mx);
    float s = e;
#pragma unroll
    for (int off = 16; off; off >>= 1) s += __shfl_xor_sync(0xffffffffu, s, off);
    if (lane == 0) red[warp] = s;
    __syncthreads();
    float sm = 0.0f;
#pragma unroll
    for (int i = 0; i < 8; i++) sm += red[i];
    g_scores[row * T + tid] = e / sm;
}

// ---------------------------------------------------------------------------
// Y[b,s,d] = sum_t attn[b,s,t] * X[b,t,d]   (per (b, 256-wide d tile))
// ---------------------------------------------------------------------------
__global__ __launch_bounds__(256) void k_Y(const float* __restrict__ X) {
    __shared__ float Xs[16][256];   // [t-sub][d]
    __shared__ float Ats[256][17];  // [t][s], padded
    int b = blockIdx.y;
    int d0b = blockIdx.x * 256;
    int tid = threadIdx.x;
#pragma unroll
    for (int i = 0; i < S; i++)
        Ats[tid][i] = g_scores[(b * S + i) * T + tid];
    int tm = tid & 63, tn = tid >> 6;
    int m0 = tm * 4, n0 = tn * 4;   // m over d(256), n over s
    float2 acc[4][2] = {};
    const float* Xb = X + b * (T * D) + d0b;
    int lk = tid >> 4, lc = (tid & 15) << 4;
    for (int t0 = 0; t0 < T; t0 += 16) {
#pragma unroll
        for (int j = 0; j < 4; j++)
            *(float4*)&Xs[lk][lc + j * 4] = *(const float4*)(Xb + (t0 + lk) * D + lc + j * 4);
        __syncthreads();
#pragma unroll
        for (int k = 0; k < 16; k++) {
            float4 a = *(const float4*)&Xs[k][m0];
            const float* brow = &Ats[t0 + k][0];
            float2 b01 = make_float2(brow[n0], brow[n0 + 1]);
            float2 b23 = make_float2(brow[n0 + 2], brow[n0 + 3]);
            float am[4] = {a.x, a.y, a.z, a.w};
#pragma unroll
            for (int i = 0; i < 4; i++) {
                float2 aa = make_float2(am[i], am[i]);
                acc[i][0] = ffma2(aa, b01, acc[i][0]);
                acc[i][1] = ffma2(aa, b23, acc[i][1]);
            }
        }
        __syncthreads();
    }
    float(*af)[4] = reinterpret_cast<float(*)[4]>(acc);
#pragma unroll
    for (int j = 0; j < 4; j++) {
        float4 v = make_float4(af[0][j], af[1][j], af[2][j], af[3][j]);
        *(float4*)(g_Y + (b * S + n0 + j) * D + d0b + m0) = v;
    }
}

// ---------------------------------------------------------------------------
// out[g,e'] = cb[e'] + sum_d Y[g,d]*Ct[d][e']   (128x128x16, 8x8/thread, f32x2)
// ---------------------------------------------------------------------------
__global__ __launch_bounds__(256, 2) void k_out(float* __restrict__ out) {
    __shared__ float As[16][128];  // [k][m]  A = Y
    __shared__ float Bs[16][128];  // [k][n]  B = Ct
    int m0b = blockIdx.y * 128, n0b = blockIdx.x * 128;
    int tid = threadIdx.x;
    int tm = tid & 15, tn = tid >> 4;
    int m0 = tm * 8, n0 = tn * 8;
    int ar = tid >> 1, ac = (tid & 1) * 8;
    int br = tid >> 4, bc = (tid & 15) * 8;
    float2 acc[8][4] = {};
    for (int k0 = 0; k0 < D; k0 += 16) {
#pragma unroll
        for (int h = 0; h < 2; h++) {
            float4 v = *(const float4*)(g_Y + (m0b + ar) * D + k0 + ac + h * 4);
            As[ac + h * 4 + 0][ar] = v.x; As[ac + h * 4 + 1][ar] = v.y;
            As[ac + h * 4 + 2][ar] = v.z; As[ac + h * 4 + 3][ar] = v.w;
        }
        *(float4*)&Bs[br][bc]     = *(const float4*)(g_Ct + (k0 + br) * D + n0b + bc);
        *(float4*)&Bs[br][bc + 4] = *(const float4*)(g_Ct + (k0 + br) * D + n0b + bc + 4);
        __syncthreads();
#pragma unroll
        for (int k = 0; k < 16; k++) {
            float4 a0 = *(const float4*)&As[k][m0];
            float4 a1 = *(const float4*)&As[k][m0 + 4];
            float4 b0 = *(const float4*)&Bs[k][n0];
            float4 b1 = *(const float4*)&Bs[k][n0 + 4];
            float am[8] = {a0.x, a0.y, a0.z, a0.w, a1.x, a1.y, a1.z, a1.w};
            float2 bp[4] = {make_float2(b0.x, b0.y), make_float2(b0.z, b0.w),
                            make_float2(b1.x, b1.y), make_float2(b1.z, b1.w)};
#pragma unroll
            for (int i = 0; i < 8; i++) {
                float2 aa = make_float2(am[i], am[i]);
#pragma unroll
                for (int p = 0; p < 4; p++) acc[i][p] = ffma2(aa, bp[p], acc[i][p]);
            }
        }
        __syncthreads();
    }
    float cbv[8];
#pragma unroll
    for (int j = 0; j < 8; j++) cbv[j] = g_cb[n0b + n0 + j];
    float(*af)[8] = reinterpret_cast<float(*)[8]>(acc);
#pragma unroll
    for (int i = 0; i < 8; i++) {
        float* o = out + (m0b + m0 + i) * D + n0b + n0;
        float4 v0 = make_float4(af[i][0] + cbv[0], af[i][1] + cbv[1],
                                af[i][2] + cbv[2], af[i][3] + cbv[3]);
        float4 v1 = make_float4(af[i][4] + cbv[4], af[i][5] + cbv[5],
                                af[i][6] + cbv[6], af[i][7] + cbv[7]);
        *(float4*)o = v0;
        *(float4*)(o + 4) = v1;
    }
}

// ---------------------------------------------------------------------------
// launch
// ---------------------------------------------------------------------------
extern "C" void kernel_launch(void* const* d_in, const int* in_sizes, int n_in,
                              void* d_out, int out_size) {
    const float* X      = (const float*)d_in[0];   // segment_states [512,256,1024]
    const float* imp    = (const float*)d_in[1];   // importance_logits [512,256]
    const float* latent = (const float*)d_in[2];   // latent_queries [16,1024]
    const float* Wq     = (const float*)d_in[3];
    const float* bq     = (const float*)d_in[4];
    const float* Wk     = (const float*)d_in[5];
    const float* bk     = (const float*)d_in[6];
    const float* Wv     = (const float*)d_in[7];
    const float* bv     = (const float*)d_in[8];
    const float* Wo     = (const float*)d_in[9];
    const float* bo     = (const float*)d_in[10];
    float* out = (float*)d_out;                    // [512,16,1024]

    k_zeroqk<<<64, 256>>>();
    k_q<<<128, 256>>>(latent, Wq, bq);
    k_qb<<<1, 512>>>(bk);
    k_qk<<<dim3(4, 16), 256>>>(Wk);
    k_C<<<dim3(16, 16), 256>>>(Wo, Wv);
    k_cb<<<128, 256>>>(Wo, bv, bo);
    k_scores<<<512, 256>>>(X, imp);
    k_softmax<<<B * S, 256>>>();
    k_Y<<<dim3(4, B), 256>>>(X);
    k_out<<<dim3(8, 64), 256>>>(out);
}

// round 14
// speedup vs baseline: 1.0006x; 1.0006x over previous
#include <cuda_runtime.h>
#include <math.h>

// Problem constants
#define D     1024
#define S     16
#define B     512
#define T     256
#define SCALE 0.03125f   // 1/sqrt(1024)

// ---------------------------------------------------------------------------
// Scratch (device globals — no allocations allowed)
// ---------------------------------------------------------------------------
__device__ float g_q[S * D];          // q = latent @ Wq^T + bq            [16,1024]
__device__ float g_qk[S * D];         // scale * (q @ Wk)                  [16,1024]
__device__ float g_qb[S];             // scale * (q . bk)                  [16]
__device__ float g_Ct[D * D];         // Ct[d][e'] = sum_e Wo[e',e]Wv[e,d] [1024,1024]
__device__ float g_cb[D];             // Wo @ bv + bo                      [1024]
__device__ float g_scores[B * S * T]; // scores -> attn (in place)         [512,16,256]
__device__ float g_Y[B * S * D];      // Y = attn @ X                      [512,16,1024]

// ---------------------------------------------------------------------------
// packed f32x2 FMA (sm_103a): d = a*b + c on two fp32 lanes
// ---------------------------------------------------------------------------
__device__ __forceinline__ float2 ffma2(float2 a, float2 b, float2 c) {
    unsigned long long ra = *reinterpret_cast<unsigned long long*>(&a);
    unsigned long long rb = *reinterpret_cast<unsigned long long*>(&b);
    unsigned long long rc = *reinterpret_cast<unsigned long long*>(&c);
    unsigned long long rd;
    asm("fma.rn.f32x2 %0, %1, %2, %3;" : "=l"(rd) : "l"(ra), "l"(rb), "l"(rc));
    float2 d;
    *reinterpret_cast<unsigned long long*>(&d) = rd;
    return d;
}

// ---------------------------------------------------------------------------
// zero g_qk (needed before the atomic split-K accumulation)
// ---------------------------------------------------------------------------
__global__ void k_zeroqk() {
    g_qk[blockIdx.x * 256 + threadIdx.x] = 0.0f;
}

// ---------------------------------------------------------------------------
// q[s,e] = sum_d latent[s,d] * Wq[e,d] + bq[e]   (warp per e, all 16 s)
// ---------------------------------------------------------------------------
__global__ __launch_bounds__(256) void k_q(const float* __restrict__ latent,
                                           const float* __restrict__ Wq,
                                           const float* __restrict__ bq) {
    int warp = (blockIdx.x * blockDim.x + threadIdx.x) >> 5;  // 0..1023 == e
    int lane = threadIdx.x & 31;
    const float* wrow = Wq + warp * D;
    float acc[S];
#pragma unroll
    for (int s = 0; s < S; s++) acc[s] = 0.0f;
    for (int i = 0; i < D / 32; i++) {
        int d = (i << 5) + lane;
        float w = wrow[d];
#pragma unroll
        for (int s = 0; s < S; s++) acc[s] += w * latent[s * D + d];
    }
#pragma unroll
    for (int s = 0; s < S; s++) {
        float v = acc[s];
#pragma unroll
        for (int off = 16; off; off >>= 1) v += __shfl_xor_sync(0xffffffffu, v, off);
        if (lane == 0) g_q[s * D + warp] = v + bq[warp];
    }
}

// qb[s] = scale * (q[s,:] . bk)
__global__ void k_qb(const float* __restrict__ bk) {
    int warp = threadIdx.x >> 5, lane = threadIdx.x & 31;
    if (warp >= S) return;
    float acc = 0.0f;
    for (int i = lane; i < D; i += 32) acc += g_q[warp * D + i] * bk[i];
#pragma unroll
    for (int off = 16; off; off >>= 1) acc += __shfl_xor_sync(0xffffffffu, acc, off);
    if (lane == 0) g_qb[warp] = acc * SCALE;
}

// qk[s,d] = scale * sum_e q[s,e] * Wk[e,d]   (split over e blocks, atomic add)
__global__ __launch_bounds__(256) void k_qk(const float* __restrict__ Wk) {
    __shared__ float qs[S][64];
    int d  = blockIdx.x * 256 + threadIdx.x;  // 0..1023
    int e0 = blockIdx.y * 64;
    {   // stage q tile [16][64]
        int idx = threadIdx.x;
#pragma unroll
        for (int j = 0; j < 4; j++) {
            int ii = idx + j * 256;
            qs[ii >> 6][ii & 63] = g_q[(ii >> 6) * D + e0 + (ii & 63)];
        }
    }
    __syncthreads();
    float acc[S];
#pragma unroll
    for (int s = 0; s < S; s++) acc[s] = 0.0f;
    for (int e = 0; e < 64; e++) {
        float w = Wk[(e0 + e) * D + d];
#pragma unroll
        for (int s = 0; s < S; s++) acc[s] += w * qs[s][e];
    }
#pragma unroll
    for (int s = 0; s < S; s++) atomicAdd(&g_qk[s * D + d], acc[s] * SCALE);
}

// ---------------------------------------------------------------------------
// Ct[d][e'] = sum_e Wo[e',e] * Wv[e,d]   (64x64x16 tile, 4x4/thread, f32x2)
// ---------------------------------------------------------------------------
__global__ __launch_bounds__(256) void k_C(const float* __restrict__ Wo,
                                           const float* __restrict__ Wv) {
    __shared__ float As[16][64];  // [k][m]  m = e'
    __shared__ float Bs[16][64];  // [k][n]  n = d
    int tid = threadIdx.x;
    int m0b = blockIdx.y * 64, n0b = blockIdx.x * 64;
    int tm = tid & 15, tn = tid >> 4;
    int m0 = tm * 4, n0 = tn * 4;
    int ar = tid >> 2, ac = (tid & 3) * 4;
    int br = tid >> 4, bn = (tid & 15) * 4;
    float2 acc[4][2] = {};
    for (int k0 = 0; k0 < D; k0 += 16) {
        float4 av = *(const float4*)(Wo + (m0b + ar) * D + k0 + ac);
        As[ac + 0][ar] = av.x; As[ac + 1][ar] = av.y;
        As[ac + 2][ar] = av.z; As[ac + 3][ar] = av.w;
        *(float4*)&Bs[br][bn] = *(const float4*)(Wv + (k0 + br) * D + n0b + bn);
        __syncthreads();
#pragma unroll
        for (int k = 0; k < 16; k++) {
            float4 a  = *(const float4*)&As[k][m0];
            float4 bb = *(const float4*)&Bs[k][n0];
            float2 b01 = make_float2(bb.x, bb.y), b23 = make_float2(bb.z, bb.w);
            float am[4] = {a.x, a.y, a.z, a.w};
#pragma unroll
            for (int i = 0; i < 4; i++) {
                float2 aa = make_float2(am[i], am[i]);
                acc[i][0] = ffma2(aa, b01, acc[i][0]);
                acc[i][1] = ffma2(aa, b23, acc[i][1]);
            }
        }
        __syncthreads();
    }
    float(*af)[4] = reinterpret_cast<float(*)[4]>(acc);
#pragma unroll
    for (int j = 0; j < 4; j++) {
        float4 v = make_float4(af[0][j], af[1][j], af[2][j], af[3][j]);
        *(float4*)(g_Ct + (n0b + n0 + j) * D + m0b + m0) = v;
    }
}

// cb[e'] = sum_e Wo[e',e]*bv[e] + bo[e']   (warp per e')
__global__ __launch_bounds__(256) void k_cb(const float* __restrict__ Wo,
                                            const float* __restrict__ bv,
                                            const float* __restrict__ bo) {
    int warp = (blockIdx.x * blockDim.x + threadIdx.x) >> 5;  // 0..1023
    int lane = threadIdx.x & 31;
    float acc = 0.0f;
    for (int i = lane; i < D; i += 32) acc += Wo[warp * D + i] * bv[i];
#pragma unroll
    for (int off = 16; off; off >>= 1) acc += __shfl_xor_sync(0xffffffffu, acc, off);
    if (lane == 0) g_cb[warp] = acc + bo[warp];
}

// ---------------------------------------------------------------------------
// scores[b,s,t] = qk[s,:].X[b,t,:] + qb[s] + imp[b,t]   (per-batch GEMM, N=16)
// ---------------------------------------------------------------------------
__global__ __launch_bounds__(256) void k_scores(const float* __restrict__ X,
                                                const float* __restrict__ imp) {
    __shared__ float Xs[16][256];   // [k (d-sub)][t]
    __shared__ float qks[16][16];   // [k][s]
    int b   = blockIdx.x;
    int tid = threadIdx.x;
    const float* Xb = X + b * (T * D);
    int tm = tid & 63, tn = tid >> 6;
    int m0 = tm * 4, n0 = tn * 4;     // m over t, n over s
    float2 acc[4][2] = {};
    for (int k0 = 0; k0 < D; k0 += 16) {
#pragma unroll
        for (int j = 0; j < 4; j++) {
            float4 v = *(const float4*)(Xb + tid * D + k0 + j * 4);
            Xs[j * 4 + 0][tid] = v.x; Xs[j * 4 + 1][tid] = v.y;
            Xs[j * 4 + 2][tid] = v.z; Xs[j * 4 + 3][tid] = v.w;
        }
        qks[tid & 15][tid >> 4] = g_qk[(tid >> 4) * D + k0 + (tid & 15)];
        __syncthreads();
#pragma unroll
        for (int k = 0; k < 16; k++) {
            float4 a  = *(const float4*)&Xs[k][m0];
            float4 bq = *(const float4*)&qks[k][n0];
            float2 b01 = make_float2(bq.x, bq.y), b23 = make_float2(bq.z, bq.w);
            float am[4] = {a.x, a.y, a.z, a.w};
#pragma unroll
            for (int i = 0; i < 4; i++) {
                float2 aa = make_float2(am[i], am[i]);
                acc[i][0] = ffma2(aa, b01, acc[i][0]);
                acc[i][1] = ffma2(aa, b23, acc[i][1]);
            }
        }
        __syncthreads();
    }
    float4 iv = *(const float4*)(imp + b * T + m0);
    float(*af)[4] = reinterpret_cast<float(*)[4]>(acc);
#pragma unroll
    for (int j = 0; j < 4; j++) {
        int s = n0 + j;
        float qb = g_qb[s];
        float4 v = make_float4(af[0][j] + qb + iv.x, af[1][j] + qb + iv.y,
                               af[2][j] + qb + iv.z, af[3][j] + qb + iv.w);
        *(float4*)(g_scores + (b * S + s) * T + m0) = v;
    }
}

// ---------------------------------------------------------------------------
// softmax over t (row = b*16+s, 256 threads = 256 t)
// ---------------------------------------------------------------------------
__global__ __launch_bounds__(256) void k_softmax() {
    int row = blockIdx.x;
    int tid = threadIdx.x;
    int warp = tid >> 5, lane = tid & 31;
    __shared__ float red[8];
    float v = g_scores[row * T + tid];
    float m = v;
#pragma unroll
    for (int off = 16; off; off >>= 1) m = fmaxf(m, __shfl_xor_sync(0xffffffffu, m, off));
    if (lane == 0) red[warp] = m;
    __syncthreads();
    float mx = red[0];
#pragma unroll
    for (int i = 1; i < 8; i++) mx = fmaxf(mx, red[i]);
    __syncthreads();
    float e = expf(v - mx);
    float s = e;
#pragma unroll
    for (int off = 16; off; off >>= 1) s += __shfl_xor_sync(0xffffffffu, s, off);
    if (lane == 0) red[warp] = s;
    __syncthreads();
    float sm = 0.0f;
#pragma unroll
    for (int i = 0; i < 8; i++) sm += red[i];
    g_scores[row * T + tid] = e / sm;
}

// ---------------------------------------------------------------------------
// Y[b,s,d] = sum_t attn[b,s,t] * X[b,t,d]   (per (b, 256-wide d tile))
// ---------------------------------------------------------------------------
__global__ __launch_bounds__(256) void k_Y(const float* __restrict__ X) {
    __shared__ float Xs[16][256];   // [t-sub][d]
    __shared__ float Ats[256][17];  // [t][s], padded
    int b = blockIdx.y;
    int d0b = blockIdx.x * 256;
    int tid = threadIdx.x;
#pragma unroll
    for (int i = 0; i < S; i++)
        Ats[tid][i] = g_scores[(b * S + i) * T + tid];
    int tm = tid & 63, tn = tid >> 6;
    int m0 = tm * 4, n0 = tn * 4;   // m over d(256), n over s
    float2 acc[4][2] = {};
    const float* Xb = X + b * (T * D) + d0b;
    int lk = tid >> 4, lc = (tid & 15) << 4;
    for (int t0 = 0; t0 < T; t0 += 16) {
#pragma unroll
        for (int j = 0; j < 4; j++)
            *(float4*)&Xs[lk][lc + j * 4] = *(const float4*)(Xb + (t0 + lk) * D + lc + j * 4);
        __syncthreads();
#pragma unroll
        for (int k = 0; k < 16; k++) {
            float4 a = *(const float4*)&Xs[k][m0];
            const float* brow = &Ats[t0 + k][0];
            float2 b01 = make_float2(brow[n0], brow[n0 + 1]);
            float2 b23 = make_float2(brow[n0 + 2], brow[n0 + 3]);
            float am[4] = {a.x, a.y, a.z, a.w};
#pragma unroll
            for (int i = 0; i < 4; i++) {
                float2 aa = make_float2(am[i], am[i]);
                acc[i][0] = ffma2(aa, b01, acc[i][0]);
                acc[i][1] = ffma2(aa, b23, acc[i][1]);
            }
        }
        __syncthreads();
    }
    float(*af)[4] = reinterpret_cast<float(*)[4]>(acc);
#pragma unroll
    for (int j = 0; j < 4; j++) {
        float4 v = make_float4(af[0][j], af[1][j], af[2][j], af[3][j]);
        *(float4*)(g_Y + (b * S + n0 + j) * D + d0b + m0) = v;
    }
}

// ---------------------------------------------------------------------------
// out[g,e'] = cb[e'] + sum_d Y[g,d]*Ct[d][e']   (128x128x16, 8x8/thread, f32x2)
// ---------------------------------------------------------------------------
__global__ __launch_bounds__(256, 2) void k_out(float* __restrict__ out) {
    __shared__ float As[16][128];  // [k][m]  A = Y
    __shared__ float Bs[16][128];  // [k][n]  B = Ct
    int m0b = blockIdx.y * 128, n0b = blockIdx.x * 128;
    int tid = threadIdx.x;
    int tm = tid & 15, tn = tid >> 4;
    int m0 = tm * 8, n0 = tn * 8;
    int ar = tid >> 1, ac = (tid & 1) * 8;
    int br = tid >> 4, bc = (tid & 15) * 8;
    float2 acc[8][4] = {};
    for (int k0 = 0; k0 < D; k0 += 16) {
#pragma unroll
        for (int h = 0; h < 2; h++) {
            float4 v = *(const float4*)(g_Y + (m0b + ar) * D + k0 + ac + h * 4);
            As[ac + h * 4 + 0][ar] = v.x; As[ac + h * 4 + 1][ar] = v.y;
            As[ac + h * 4 + 2][ar] = v.z; As[ac + h * 4 + 3][ar] = v.w;
        }
        *(float4*)&Bs[br][bc]     = *(const float4*)(g_Ct + (k0 + br) * D + n0b + bc);
        *(float4*)&Bs[br][bc + 4] = *(const float4*)(g_Ct + (k0 + br) * D + n0b + bc + 4);
        __syncthreads();
#pragma unroll
        for (int k = 0; k < 16; k++) {
            float4 a0 = *(const float4*)&As[k][m0];
            float4 a1 = *(const float4*)&As[k][m0 + 4];
            float4 b0 = *(const float4*)&Bs[k][n0];
            float4 b1 = *(const float4*)&Bs[k][n0 + 4];
            float am[8] = {a0.x, a0.y, a0.z, a0.w, a1.x, a1.y, a1.z, a1.w};
            float2 bp[4] = {make_float2(b0.x, b0.y), make_float2(b0.z, b0.w),
                            make_float2(b1.x, b1.y), make_float2(b1.z, b1.w)};
#pragma unroll
            for (int i = 0; i < 8; i++) {
                float2 aa = make_float2(am[i], am[i]);
#pragma unroll
                for (int p = 0; p < 4; p++) acc[i][p] = ffma2(aa, bp[p], acc[i][p]);
            }
        }
        __syncthreads();
    }
    float cbv[8];
#pragma unroll
    for (int j = 0; j < 8; j++) cbv[j] = g_cb[n0b + n0 + j];
    float(*af)[8] = reinterpret_cast<float(*)[8]>(acc);
#pragma unroll
    for (int i = 0; i < 8; i++) {
        float* o = out + (m0b + m0 + i) * D + n0b + n0;
        float4 v0 = make_float4(af[i][0] + cbv[0], af[i][1] + cbv[1],
                                af[i][2] + cbv[2], af[i][3] + cbv[3]);
        float4 v1 = make_float4(af[i][4] + cbv[4], af[i][5] + cbv[5],
                                af[i][6] + cbv[6], af[i][7] + cbv[7]);
        *(float4*)o = v0;
        *(float4*)(o + 4) = v1;
    }
}

// ---------------------------------------------------------------------------
// launch
// ---------------------------------------------------------------------------
extern "C" void kernel_launch(void* const* d_in, const int* in_sizes, int n_in,
                              void* d_out, int out_size) {
    const float* X      = (const float*)d_in[0];   // segment_states [512,256,1024]
    const float* imp    = (const float*)d_in[1];   // importance_logits [512,256]
    const float* latent = (const float*)d_in[2];   // latent_queries [16,1024]
    const float* Wq     = (const float*)d_in[3];
    const float* bq     = (const float*)d_in[4];
    const float* Wk     = (const float*)d_in[5];
    const float* bk     = (const float*)d_in[6];
    const float* Wv     = (const float*)d_in[7];
    const float* bv     = (const float*)d_in[8];
    const float* Wo     = (const float*)d_in[9];
    const float* bo     = (const float*)d_in[10];
    float* out = (float*)d_out;                    // [512,16,1024]

    k_zeroqk<<<64, 256>>>();
    k_q<<<128, 256>>>(latent, Wq, bq);
    k_qb<<<1, 512>>>(bk);
    k_qk<<<dim3(4, 16), 256>>>(Wk);
    k_C<<<dim3(16, 16), 256>>>(Wo, Wv);
    k_cb<<<128, 256>>>(Wo, bv, bo);
    k_scores<<<512, 256>>>(X, imp);
    k_softmax<<<B * S, 256>>>();
    k_Y<<<dim3(4, B), 256>>>(X);
    k_out<<<dim3(8, 64), 256>>>(out);
}

// round 17
// speedup vs baseline: 1.3190x; 1.3182x over previous
#include <cuda_runtime.h>
#include <cstdint>
#include <math.h>

// Problem constants
#define D     1024
#define S     16
#define B     512
#define T     256
#define SCALE 0.03125f   // 1/sqrt(1024)

// ---------------------------------------------------------------------------
// Scratch (device globals — no allocations allowed)
// ---------------------------------------------------------------------------
__device__ float g_q[S * D];          // q = latent @ Wq^T + bq            [16,1024]
__device__ float g_qk[S * D];         // scale * (q @ Wk)                  [16,1024]
__device__ float g_qb[S];             // scale * (q . bk)                  [16]
__device__ float g_C[D * D];          // C[e'][d] = sum_e Wo[e',e]Wv[e,d]  (tf32-rounded)
__device__ float g_cb[D];             // Wo @ bv + bo                      [1024]
__device__ float g_scores[B * S * T]; // scores -> attn (in place)         [512,16,256]
__device__ float g_Y[B * S * D];      // Y = attn @ X (tf32-rounded)       [8192,1024]

// ---------------------------------------------------------------------------
// helpers
// ---------------------------------------------------------------------------
__device__ __forceinline__ float2 ffma2(float2 a, float2 b, float2 c) {
    unsigned long long ra = *reinterpret_cast<unsigned long long*>(&a);
    unsigned long long rb = *reinterpret_cast<unsigned long long*>(&b);
    unsigned long long rc = *reinterpret_cast<unsigned long long*>(&c);
    unsigned long long rd;
    asm("fma.rn.f32x2 %0, %1, %2, %3;" : "=l"(rd) : "l"(ra), "l"(rb), "l"(rc));
    float2 d;
    *reinterpret_cast<unsigned long long*>(&d) = rd;
    return d;
}

__device__ __forceinline__ float round_tf32(float v) {
    uint32_t r;
    asm("cvt.rna.tf32.f32 %0, %1;" : "=r"(r) : "f"(v));
    return __uint_as_float(r);
}

// D += A * B,  m16n8k8 tf32 (A row-major, B col-major i.e. both K-contiguous)
__device__ __forceinline__ void mma_tf32(float c[4], uint32_t a0, uint32_t a1,
                                         uint32_t a2, uint32_t a3,
                                         uint32_t b0, uint32_t b1) {
    asm volatile(
        "mma.sync.aligned.m16n8k8.row.col.f32.tf32.tf32.f32 "
        "{%0,%1,%2,%3}, {%4,%5,%6,%7}, {%8,%9}, {%0,%1,%2,%3};"
        : "+f"(c[0]), "+f"(c[1]), "+f"(c[2]), "+f"(c[3])
        : "r"(a0), "r"(a1), "r"(a2), "r"(a3), "r"(b0), "r"(b1));
}

// ---------------------------------------------------------------------------
// zero g_qk (needed before the atomic split-K accumulation)
// ---------------------------------------------------------------------------
__global__ void k_zeroqk() {
    g_qk[blockIdx.x * 256 + threadIdx.x] = 0.0f;
}

// ---------------------------------------------------------------------------
// q[s,e] = sum_d latent[s,d] * Wq[e,d] + bq[e]   (warp per e, all 16 s)
// ---------------------------------------------------------------------------
__global__ __launch_bounds__(256) void k_q(const float* __restrict__ latent,
                                           const float* __restrict__ Wq,
                                           const float* __restrict__ bq) {
    int warp = (blockIdx.x * blockDim.x + threadIdx.x) >> 5;  // e
    int lane = threadIdx.x & 31;
    const float* wrow = Wq + warp * D;
    float acc[S];
#pragma unroll
    for (int s = 0; s < S; s++) acc[s] = 0.0f;
    for (int i = 0; i < D / 32; i++) {
        int d = (i << 5) + lane;
        float w = wrow[d];
#pragma unroll
        for (int s = 0; s < S; s++) acc[s] += w * latent[s * D + d];
    }
#pragma unroll
    for (int s = 0; s < S; s++) {
        float v = acc[s];
#pragma unroll
        for (int off = 16; off; off >>= 1) v += __shfl_xor_sync(0xffffffffu, v, off);
        if (lane == 0) g_q[s * D + warp] = v + bq[warp];
    }
}

// qb[s] = scale * (q[s,:] . bk)
__global__ void k_qb(const float* __restrict__ bk) {
    int warp = threadIdx.x >> 5, lane = threadIdx.x & 31;
    if (warp >= S) return;
    float acc = 0.0f;
    for (int i = lane; i < D; i += 32) acc += g_q[warp * D + i] * bk[i];
#pragma unroll
    for (int off = 16; off; off >>= 1) acc += __shfl_xor_sync(0xffffffffu, acc, off);
    if (lane == 0) g_qb[warp] = acc * SCALE;
}

// qk[s,d] = scale * sum_e q[s,e] * Wk[e,d]   (grid (4,64): 16-wide e chunks)
__global__ __launch_bounds__(256) void k_qk(const float* __restrict__ Wk) {
    __shared__ float qs[S][16];
    int d  = blockIdx.x * 256 + threadIdx.x;
    int e0 = blockIdx.y * 16;
    qs[threadIdx.x >> 4][threadIdx.x & 15] =
        g_q[(threadIdx.x >> 4) * D + e0 + (threadIdx.x & 15)];
    __syncthreads();
    float acc[S];
#pragma unroll
    for (int s = 0; s < S; s++) acc[s] = 0.0f;
#pragma unroll
    for (int e = 0; e < 16; e++) {
        float w = Wk[(e0 + e) * D + d];
#pragma unroll
        for (int s = 0; s < S; s++) acc[s] += w * qs[s][e];
    }
#pragma unroll
    for (int s = 0; s < S; s++) atomicAdd(&g_qk[s * D + d], acc[s] * SCALE);
}

// ---------------------------------------------------------------------------
// C[e'][d] = sum_e Wo[e',e] * Wv[e,d]   (64x64x16 tile, row-major out, tf32)
// ---------------------------------------------------------------------------
__global__ __launch_bounds__(256) void k_C(const float* __restrict__ Wo,
                                           const float* __restrict__ Wv) {
    __shared__ float As[16][64];  // [k][m]  m = e'
    __shared__ float Bs[16][64];  // [k][n]  n = d
    int tid = threadIdx.x;
    int m0b = blockIdx.y * 64, n0b = blockIdx.x * 64;
    int tm = tid & 15, tn = tid >> 4;
    int m0 = tm * 4, n0 = tn * 4;
    int ar = tid >> 2, ac = (tid & 3) * 4;
    int br = tid >> 4, bn = (tid & 15) * 4;
    float2 acc[4][2] = {};
    for (int k0 = 0; k0 < D; k0 += 16) {
        float4 av = *(const float4*)(Wo + (m0b + ar) * D + k0 + ac);
        As[ac + 0][ar] = av.x; As[ac + 1][ar] = av.y;
        As[ac + 2][ar] = av.z; As[ac + 3][ar] = av.w;
        *(float4*)&Bs[br][bn] = *(const float4*)(Wv + (k0 + br) * D + n0b + bn);
        __syncthreads();
#pragma unroll
        for (int k = 0; k < 16; k++) {
            float4 a  = *(const float4*)&As[k][m0];
            float4 bb = *(const float4*)&Bs[k][n0];
            float2 b01 = make_float2(bb.x, bb.y), b23 = make_float2(bb.z, bb.w);
            float am[4] = {a.x, a.y, a.z, a.w};
#pragma unroll
            for (int i = 0; i < 4; i++) {
                float2 aa = make_float2(am[i], am[i]);
                acc[i][0] = ffma2(aa, b01, acc[i][0]);
                acc[i][1] = ffma2(aa, b23, acc[i][1]);
            }
        }
        __syncthreads();
    }
    float(*af)[4] = reinterpret_cast<float(*)[4]>(acc);
#pragma unroll
    for (int i = 0; i < 4; i++) {   // row-major store, tf32-rounded
        float4 v = make_float4(round_tf32(af[i][0]), round_tf32(af[i][1]),
                               round_tf32(af[i][2]), round_tf32(af[i][3]));
        *(float4*)(g_C + (m0b + m0 + i) * D + n0b + n0) = v;
    }
}

// cb[e'] = sum_e Wo[e',e]*bv[e] + bo[e']   (warp per e')
__global__ __launch_bounds__(256) void k_cb(const float* __restrict__ Wo,
                                            const float* __restrict__ bv,
                                            const float* __restrict__ bo) {
    int warp = (blockIdx.x * blockDim.x + threadIdx.x) >> 5;
    int lane = threadIdx.x & 31;
    float acc = 0.0f;
    for (int i = lane; i < D; i += 32) acc += Wo[warp * D + i] * bv[i];
#pragma unroll
    for (int off = 16; off; off >>= 1) acc += __shfl_xor_sync(0xffffffffu, acc, off);
    if (lane == 0) g_cb[warp] = acc + bo[warp];
}

// ---------------------------------------------------------------------------
// scores[b,s,t] = qk[s,:].X[b,t,:] + qb[s] + imp[b,t]   (per-batch GEMM, N=16)
// ---------------------------------------------------------------------------
__global__ __launch_bounds__(256) void k_scores(const float* __restrict__ X,
                                                const float* __restrict__ imp) {
    __shared__ float Xs[16][256];   // [k (d-sub)][t]
    __shared__ float qks[16][16];   // [k][s]
    int b   = blockIdx.x;
    int tid = threadIdx.x;
    const float* Xb = X + b * (T * D);
    int tm = tid & 63, tn = tid >> 6;
    int m0 = tm * 4, n0 = tn * 4;     // m over t, n over s
    float2 acc[4][2] = {};
    for (int k0 = 0; k0 < D; k0 += 16) {
#pragma unroll
        for (int j = 0; j < 4; j++) {
            float4 v = *(const float4*)(Xb + tid * D + k0 + j * 4);
            Xs[j * 4 + 0][tid] = v.x; Xs[j * 4 + 1][tid] = v.y;
            Xs[j * 4 + 2][tid] = v.z; Xs[j * 4 + 3][tid] = v.w;
        }
        qks[tid & 15][tid >> 4] = g_qk[(tid >> 4) * D + k0 + (tid & 15)];
        __syncthreads();
#pragma unroll
        for (int k = 0; k < 16; k++) {
            float4 a  = *(const float4*)&Xs[k][m0];
            float4 bq = *(const float4*)&qks[k][n0];
            float2 b01 = make_float2(bq.x, bq.y), b23 = make_float2(bq.z, bq.w);
            float am[4] = {a.x, a.y, a.z, a.w};
#pragma unroll
            for (int i = 0; i < 4; i++) {
                float2 aa = make_float2(am[i], am[i]);
                acc[i][0] = ffma2(aa, b01, acc[i][0]);
                acc[i][1] = ffma2(aa, b23, acc[i][1]);
            }
        }
        __syncthreads();
    }
    float4 iv = *(const float4*)(imp + b * T + m0);
    float(*af)[4] = reinterpret_cast<float(*)[4]>(acc);
#pragma unroll
    for (int j = 0; j < 4; j++) {
        int s = n0 + j;
        float qb = g_qb[s];
        float4 v = make_float4(af[0][j] + qb + iv.x, af[1][j] + qb + iv.y,
                               af[2][j] + qb + iv.z, af[3][j] + qb + iv.w);
        *(float4*)(g_scores + (b * S + s) * T + m0) = v;
    }
}

// ---------------------------------------------------------------------------
// softmax over t (row = b*16+s, 256 threads = 256 t)
// ---------------------------------------------------------------------------
__global__ __launch_bounds__(256) void k_softmax() {
    int row = blockIdx.x;
    int tid = threadIdx.x;
    int warp = tid >> 5, lane = tid & 31;
    __shared__ float red[8];
    float v = g_scores[row * T + tid];
    float m = v;
#pragma unroll
    for (int off = 16; off; off >>= 1) m = fmaxf(m, __shfl_xor_sync(0xffffffffu, m, off));
    if (lane == 0) red[warp] = m;
    __syncthreads();
    float mx = red[0];
#pragma unroll
    for (int i = 1; i < 8; i++) mx = fmaxf(mx, red[i]);
    __syncthreads();
    float e = expf(v - mx);
    float s = e;
#pragma unroll
    for (int off = 16; off; off >>= 1) s += __shfl_xor_sync(0xffffffffu, s, off);
    if (lane == 0) red[warp] = s;
    __syncthreads();
    float sm = 0.0f;
#pragma unroll
    for (int i = 0; i < 8; i++) sm += red[i];
    g_scores[row * T + tid] = e / sm;
}

// ---------------------------------------------------------------------------
// Y[b,s,d] = sum_t attn[b,s,t] * X[b,t,d]  (tf32-rounded output)
// ---------------------------------------------------------------------------
__global__ __launch_bounds__(256) void k_Y(const float* __restrict__ X) {
    __shared__ float Xs[16][256];   // [t-sub][d]
    __shared__ float Ats[256][17];  // [t][s], padded
    int b = blockIdx.y;
    int d0b = blockIdx.x * 256;
    int tid = threadIdx.x;
#pragma unroll
    for (int i = 0; i < S; i++)
        Ats[tid][i] = g_scores[(b * S + i) * T + tid];
    int tm = tid & 63, tn = tid >> 6;
    int m0 = tm * 4, n0 = tn * 4;   // m over d(256), n over s
    float2 acc[4][2] = {};
    const float* Xb = X + b * (T * D) + d0b;
    int lk = tid >> 4, lc = (tid & 15) << 4;
    for (int t0 = 0; t0 < T; t0 += 16) {
#pragma unroll
        for (int j = 0; j < 4; j++)
            *(float4*)&Xs[lk][lc + j * 4] = *(const float4*)(Xb + (t0 + lk) * D + lc + j * 4);
        __syncthreads();
#pragma unroll
        for (int k = 0; k < 16; k++) {
            float4 a = *(const float4*)&Xs[k][m0];
            const float* brow = &Ats[t0 + k][0];
            float2 b01 = make_float2(brow[n0], brow[n0 + 1]);
            float2 b23 = make_float2(brow[n0 + 2], brow[n0 + 3]);
            float am[4] = {a.x, a.y, a.z, a.w};
#pragma unroll
            for (int i = 0; i < 4; i++) {
                float2 aa = make_float2(am[i], am[i]);
                acc[i][0] = ffma2(aa, b01, acc[i][0]);
                acc[i][1] = ffma2(aa, b23, acc[i][1]);
            }
        }
        __syncthreads();
    }
    float(*af)[4] = reinterpret_cast<float(*)[4]>(acc);
#pragma unroll
    for (int j = 0; j < 4; j++) {
        float4 v = make_float4(round_tf32(af[0][j]), round_tf32(af[1][j]),
                               round_tf32(af[2][j]), round_tf32(af[3][j]));
        *(float4*)(g_Y + (b * S + n0 + j) * D + d0b + m0) = v;
    }
}

// ---------------------------------------------------------------------------
// out[g,e'] = cb[e'] + sum_d Y[g,d]*C[e',d]
// 128x128 tile, 8 warps (2m x 4n), m16n8k8 tf32 MMA, K-chunk 32.
// Y and C are pre-rounded to tf32 (rna) so HMMA truncation is exact.
// ---------------------------------------------------------------------------
__global__ __launch_bounds__(256, 2) void k_out(float* __restrict__ out) {
    __shared__ float As[128][36];   // Y tile  [m][k], padded
    __shared__ float Bs[128][36];   // C tile  [n][k], padded
    int tid = threadIdx.x;
    int m0b = blockIdx.y * 128, n0b = blockIdx.x * 128;
    int w = tid >> 5, lane = tid & 31;
    int wm = w & 1, wn = w >> 1;           // warp tile: 64m x 32n
    int tg = lane >> 2, t4 = lane & 3;
    float c[4][4][4] = {};                 // [mfrag][nfrag][reg]
    int srow = tid >> 1, scol = (tid & 1) * 16;
    for (int k0 = 0; k0 < D; k0 += 32) {
#pragma unroll
        for (int j = 0; j < 4; j++) {
            *(float4*)&As[srow][scol + j * 4] =
                *(const float4*)(g_Y + (m0b + srow) * D + k0 + scol + j * 4);
            *(float4*)&Bs[srow][scol + j * 4] =
                *(const float4*)(g_C + (n0b + srow) * D + k0 + scol + j * 4);
        }
        __syncthreads();
#pragma unroll
        for (int ks = 0; ks < 4; ks++) {
            int kk = ks * 8;
            uint32_t bfr[4][2];
#pragma unroll
            for (int nf = 0; nf < 4; nf++) {
                int n = wn * 32 + nf * 8 + tg;
                bfr[nf][0] = __float_as_uint(Bs[n][kk + t4]);
                bfr[nf][1] = __float_as_uint(Bs[n][kk + t4 + 4]);
            }
#pragma unroll
            for (int mf = 0; mf < 4; mf++) {
                int m = wm * 64 + mf * 16 + tg;
                uint32_t a0 = __float_as_uint(As[m][kk + t4]);
                uint32_t a1 = __float_as_uint(As[m + 8][kk + t4]);
                uint32_t a2 = __float_as_uint(As[m][kk + t4 + 4]);
                uint32_t a3 = __float_as_uint(As[m + 8][kk + t4 + 4]);
#pragma unroll
                for (int nf = 0; nf < 4; nf++)
                    mma_tf32(c[mf][nf], a0, a1, a2, a3, bfr[nf][0], bfr[nf][1]);
            }
        }
        __syncthreads();
    }
#pragma unroll
    for (int mf = 0; mf < 4; mf++) {
#pragma unroll
        for (int nf = 0; nf < 4; nf++) {
            int gcol = n0b + wn * 32 + nf * 8 + 2 * t4;
            float2 cb2 = *(const float2*)(g_cb + gcol);
            int r0 = m0b + wm * 64 + mf * 16 + tg;
            float2 v0 = make_float2(c[mf][nf][0] + cb2.x, c[mf][nf][1] + cb2.y);
            float2 v1 = make_float2(c[mf][nf][2] + cb2.x, c[mf][nf][3] + cb2.y);
            *(float2*)(out + r0 * D + gcol) = v0;
            *(float2*)(out + (r0 + 8) * D + gcol) = v1;
        }
    }
}

// ---------------------------------------------------------------------------
// launch
// ---------------------------------------------------------------------------
extern "C" void kernel_launch(void* const* d_in, const int* in_sizes, int n_in,
                              void* d_out, int out_size) {
    const float* X      = (const float*)d_in[0];   // segment_states [512,256,1024]
    const float* imp    = (const float*)d_in[1];   // importance_logits [512,256]
    const float* latent = (const float*)d_in[2];   // latent_queries [16,1024]
    const float* Wq     = (const float*)d_in[3];
    const float* bq     = (const float*)d_in[4];
    const float* Wk     = (const float*)d_in[5];
    const float* bk     = (const float*)d_in[6];
    const float* Wv     = (const float*)d_in[7];
    const float* bv     = (const float*)d_in[8];
    const float* Wo     = (const float*)d_in[9];
    const float* bo     = (const float*)d_in[10];
    float* out = (float*)d_out;                    // [512,16,1024]

    k_zeroqk<<<64, 256>>>();
    k_q<<<128, 256>>>(latent, Wq, bq);
    k_qb<<<1, 512>>>(bk);
    k_qk<<<dim3(4, 64), 256>>>(Wk);
    k_C<<<dim3(16, 16), 256>>>(Wo, Wv);
    k_cb<<<128, 256>>>(Wo, bv, bo);
    k_scores<<<512, 256>>>(X, imp);
    k_softmax<<<B * S, 256>>>();
    k_Y<<<dim3(4, B), 256>>>(X);
    k_out<<<dim3(8, 64), 256>>>(out);
}